// round 11
// baseline (speedup 1.0000x reference)
#include <cuda_runtime.h>
#include <cuda_bf16.h>

// out[i,j] = dot(z1[i], z2[j]) if batch[i]==batch[j] && cls[i]==cls[j]
//            && !(24<=cls[i]<=26) && i!=j, else 0.
//
// Dual-engine fill: the copy engine (cudaMemsetAsync ~7.2TB/s) zeroes rows
// [R,N) while SMs (capped ~5.5TB/s for STG streams) run the fused
// sparse+fill+overwrite kernel on rows [0,R) on a forked capture branch.
// Warps assigned to rows >= R compute their dot products into a compact
// (row,col,val) list instead (disjoint from out). After the join, a small
// replay kernel scatters that list into the CE-zeroed region.

#define CAP 64               // max matches per row (proven sufficient in R4)

__device__ int   g_npairs;          // compact pair count (CE zone)
__device__ int2  g_rc [1 << 20];    // (row, col)
__device__ float g_pv [1 << 20];    // value

__device__ __forceinline__ int lower_bound_dev(const int* __restrict__ a, int n, int v) {
    int lo = 0, hi = n;
    while (lo < hi) { int m = (lo + hi) >> 1; if (a[m] < v) lo = m + 1; else hi = m; }
    return lo;
}
__device__ __forceinline__ int upper_bound_dev(const int* __restrict__ a, int n, int v) {
    int lo = 0, hi = n;
    while (lo < hi) { int m = (lo + hi) >> 1; if (a[m] <= v) lo = m + 1; else hi = m; }
    return lo;
}
__device__ __forceinline__ float warp_reduce_add(float d) {
    d += __shfl_xor_sync(0xffffffffu, d, 16);
    d += __shfl_xor_sync(0xffffffffu, d, 8);
    d += __shfl_xor_sync(0xffffffffu, d, 4);
    d += __shfl_xor_sync(0xffffffffu, d, 2);
    d += __shfl_xor_sync(0xffffffffu, d, 1);
    return d;
}

// One warp per row. rows < R: fused sparse+fill+overwrite (round-10 style).
// rows >= R: sparse dots appended to the compact pair list (warp-aggregated
// atomics); out untouched (CE memset owns that region concurrently).
__global__ void __launch_bounds__(256)
fused_split_d128(const float* __restrict__ z1,
                 const float* __restrict__ z2,
                 const int*  __restrict__ cls,
                 const int*  __restrict__ batch,
                 float* __restrict__ out,
                 int N, int R)
{
    __shared__ int   scol[8][CAP];
    __shared__ float sval[8][CAP];

    const int lane = threadIdx.x & 31;
    const int w    = threadIdx.x >> 5;
    const int row  = (blockIdx.x * blockDim.x + threadIdx.x) >> 5;
    if (row >= N) return;

    const bool fillRole = (row < R);
    const int ci = cls[row];
    int k = 0;

    if (!(ci >= 24 && ci <= 26)) {
        const int bi = batch[row];
        const int lo = lower_bound_dev(batch, N, bi);
        const int hi = upper_bound_dev(batch, N, bi);
        const float4 a  = reinterpret_cast<const float4*>(z1 + (size_t)row * 128)[lane];
        const float4 zv = make_float4(0.f, 0.f, 0.f, 0.f);

        for (int jb = lo; jb < hi; jb += 32) {
            const int j = jb + lane;
            const bool p = (j < hi) && (j != row) && (cls[j] == ci);
            unsigned m = __ballot_sync(0xffffffffu, p);
            while (m) {
                int jj0 = jb + __ffs(m) - 1; m &= m - 1;
                int jj1 = -1, jj2 = -1, jj3 = -1;
                if (m) { jj1 = jb + __ffs(m) - 1; m &= m - 1; }
                if (m) { jj2 = jb + __ffs(m) - 1; m &= m - 1; }
                if (m) { jj3 = jb + __ffs(m) - 1; m &= m - 1; }

                float4 v0 = reinterpret_cast<const float4*>(z2 + (size_t)jj0 * 128)[lane];
                float4 v1 = (jj1 >= 0) ? reinterpret_cast<const float4*>(z2 + (size_t)jj1 * 128)[lane] : zv;
                float4 v2 = (jj2 >= 0) ? reinterpret_cast<const float4*>(z2 + (size_t)jj2 * 128)[lane] : zv;
                float4 v3 = (jj3 >= 0) ? reinterpret_cast<const float4*>(z2 + (size_t)jj3 * 128)[lane] : zv;

                float d0 = a.x * v0.x + a.y * v0.y + a.z * v0.z + a.w * v0.w;
                float d1 = a.x * v1.x + a.y * v1.y + a.z * v1.z + a.w * v1.w;
                float d2 = a.x * v2.x + a.y * v2.y + a.z * v2.z + a.w * v2.w;
                float d3 = a.x * v3.x + a.y * v3.y + a.z * v3.z + a.w * v3.w;

                d0 = warp_reduce_add(d0);
                d1 = warp_reduce_add(d1);
                d2 = warp_reduce_add(d2);
                d3 = warp_reduce_add(d3);

                if (lane == 0) {
                    if (k < CAP)                 { scol[w][k]     = jj0; sval[w][k]     = d0; }
                    if (jj1 >= 0 && k + 1 < CAP) { scol[w][k + 1] = jj1; sval[w][k + 1] = d1; }
                    if (jj2 >= 0 && k + 2 < CAP) { scol[w][k + 2] = jj2; sval[w][k + 2] = d2; }
                    if (jj3 >= 0 && k + 3 < CAP) { scol[w][k + 3] = jj3; sval[w][k + 3] = d3; }
                }
                k += 1 + (jj1 >= 0) + (jj2 >= 0) + (jj3 >= 0);
            }
        }
    }
    __syncwarp();
    const int kk = min(k, CAP);

    if (fillRole) {
        // ---- zero-fill this row (streaming stores), then overwrite -------
        float4* orow4 = reinterpret_cast<float4*>(out + (size_t)row * (size_t)N);
        const int n4 = N >> 2;
        const float4 z = make_float4(0.f, 0.f, 0.f, 0.f);
        #pragma unroll 16
        for (int i = lane; i < n4; i += 32) __stcs(orow4 + i, z);
        __syncwarp();

        float* orow = out + (size_t)row * (size_t)N;
        for (int s = lane; s < kk; s += 32)
            orow[scol[w][s]] = sval[w][s];
    } else {
        // ---- CE zone: append to the compact pair list --------------------
        int base = 0;
        if (lane == 0 && kk > 0) base = atomicAdd(&g_npairs, kk);
        base = __shfl_sync(0xffffffffu, base, 0);
        for (int s = lane; s < kk; s += 32) {
            const int slot = base + s;
            g_rc[slot] = make_int2(row, scol[w][s]);
            g_pv[slot] = sval[w][s];
        }
    }
}

__global__ void zero_pair_count() { g_npairs = 0; }

// Post-join replay: thread per pair; two coalesced loads + one scattered STG.
__global__ void __launch_bounds__(256)
replay_pairs(float* __restrict__ out, int N)
{
    const int t = blockIdx.x * blockDim.x + threadIdx.x;
    const int n = g_npairs;
    if (t < n) {
        const int2 rc = g_rc[t];
        out[(size_t)rc.x * (size_t)N + (size_t)rc.y] = g_pv[t];
    }
}

// ----------------- generic fallback (any D): memset + direct scatter -------
__global__ void seg_decoder_sparse_generic(const float* __restrict__ z1,
                                           const float* __restrict__ z2,
                                           const int*  __restrict__ cls,
                                           const int*  __restrict__ batch,
                                           float* __restrict__ out,
                                           int N, int D)
{
    const int lane = threadIdx.x & 31;
    const int row  = (blockIdx.x * blockDim.x + threadIdx.x) >> 5;
    if (row >= N) return;

    const int ci = cls[row];
    if (ci >= 24 && ci <= 26) return;
    const int bi = batch[row];
    const int lo = lower_bound_dev(batch, N, bi);
    const int hi = upper_bound_dev(batch, N, bi);
    const float* arow = z1 + (size_t)row * D;
    float* orow = out + (size_t)row * (size_t)N;

    for (int jb = lo; jb < hi; jb += 32) {
        const int j = jb + lane;
        const bool p = (j < hi) && (j != row) && (cls[j] == ci);
        unsigned m = __ballot_sync(0xffffffffu, p);
        while (m) {
            const int b = __ffs(m) - 1; m &= m - 1;
            const int jj = jb + b;
            const float* vrow = z2 + (size_t)jj * D;
            float d = 0.f;
            for (int kkk = lane; kkk < D; kkk += 32) d += arow[kkk] * vrow[kkk];
            d = warp_reduce_add(d);
            if (lane == 0) orow[jj] = d;
        }
    }
}

extern "C" void kernel_launch(void* const* d_in, const int* in_sizes, int n_in,
                              void* d_out, int out_size)
{
    const float* z1    = (const float*)d_in[0];
    const float* z2    = (const float*)d_in[1];
    const int*   cls   = (const int*)d_in[2];
    const int*   batch = (const int*)d_in[3];
    float*       out   = (float*)d_out;

    const int N = in_sizes[2];
    const int D = in_sizes[0] / N;

    if (D == 128 && (N & 7) == 0) {
        // SM zone sized so SM fill time (~5.5TB/s + prologue) matches CE time
        // (~7.2TB/s): R ~= 0.375 * N, rounded to 8 rows (one CTA's warps).
        const int R = ((int)(N * 3 / 8) + 7) & ~7;     // 4608 for N=12288
        const int blocks = (N * 32 + 255) / 256;       // warp per row, all rows

        cudaStream_t s2 = 0;
        cudaEvent_t evF = 0, evJ = 0;
        bool forked =
            cudaStreamCreateWithFlags(&s2, cudaStreamNonBlocking) == cudaSuccess &&
            cudaEventCreateWithFlags(&evF, cudaEventDisableTiming) == cudaSuccess &&
            cudaEventCreateWithFlags(&evJ, cudaEventDisableTiming) == cudaSuccess;

        const size_t ceBytes = (size_t)(N - R) * (size_t)N * sizeof(float);
        float* ceBase = out + (size_t)R * (size_t)N;
        const int rblocks = ((1 << 20) + 255) / 256;   // bounded by list capacity

        if (forked) {
            cudaEventRecord(evF, 0);
            cudaStreamWaitEvent(s2, evF, 0);
            // SM branch: reset count, fused kernel (fills rows [0,R), stages rest)
            zero_pair_count<<<1, 1, 0, s2>>>();
            fused_split_d128<<<blocks, 256, 0, s2>>>(z1, z2, cls, batch, out, N, R);
            cudaEventRecord(evJ, s2);

            // CE branch: memset rows [R, N) concurrently
            cudaMemsetAsync(ceBase, 0, ceBytes, 0);

            cudaStreamWaitEvent(0, evJ, 0);
            replay_pairs<<<(N * CAP + 255) / 256 < rblocks ? (N * CAP + 255) / 256 : rblocks,
                           256>>>(out, N);
        } else {
            zero_pair_count<<<1, 1>>>();
            fused_split_d128<<<blocks, 256>>>(z1, z2, cls, batch, out, N, R);
            cudaMemsetAsync(ceBase, 0, ceBytes);
            replay_pairs<<<(N * CAP + 255) / 256 < rblocks ? (N * CAP + 255) / 256 : rblocks,
                           256>>>(out, N);
        }
    } else {
        cudaMemsetAsync(out, 0, (size_t)out_size * sizeof(float));
        const int blocks = (N * 32 + 255) / 256;
        seg_decoder_sparse_generic<<<blocks, 256>>>(z1, z2, cls, batch, out, N, D);
    }
}

// round 12
// speedup vs baseline: 1.0041x; 1.0041x over previous
#include <cuda_runtime.h>
#include <cuda_bf16.h>

// out[i,j] = dot(z1[i], z2[j]) if batch[i]==batch[j] && cls[i]==cls[j]
//            && !(24<=cls[i]<=26) && i!=j, else 0.
//
// Round-10 structure (best: 104.3us), one change: the zero-fill uses
// Blackwell 256-bit streaming stores (st.global.cs.v8.b32) — 1KB per warp
// per instruction — probing whether the ~5.7TB/s SM store rate is an
// instruction-width artifact or the HBM write wall.
//   phase 1: sparse dots -> SMEM staging   (clean L2)
//   phase 2: zero-fill row with STG.256.cs (streaming)
//   phase 3: overwrite staged values       (SMEM reads only)

#define CAP 64               // staged matches per row (avg ~9.5; tail-safe)

__device__ __forceinline__ int lower_bound_dev(const int* __restrict__ a, int n, int v) {
    int lo = 0, hi = n;
    while (lo < hi) { int m = (lo + hi) >> 1; if (a[m] < v) lo = m + 1; else hi = m; }
    return lo;
}
__device__ __forceinline__ int upper_bound_dev(const int* __restrict__ a, int n, int v) {
    int lo = 0, hi = n;
    while (lo < hi) { int m = (lo + hi) >> 1; if (a[m] <= v) lo = m + 1; else hi = m; }
    return lo;
}
__device__ __forceinline__ float warp_reduce_add(float d) {
    d += __shfl_xor_sync(0xffffffffu, d, 16);
    d += __shfl_xor_sync(0xffffffffu, d, 8);
    d += __shfl_xor_sync(0xffffffffu, d, 4);
    d += __shfl_xor_sync(0xffffffffu, d, 2);
    d += __shfl_xor_sync(0xffffffffu, d, 1);
    return d;
}

// 256-bit streaming zero store (sm_100+ v8 vector store).
__device__ __forceinline__ void stg256_zero_cs(float* p) {
    asm volatile("st.global.cs.v8.b32 [%0], {%1,%1,%1,%1,%1,%1,%1,%1};"
                 :: "l"(p), "r"(0u) : "memory");
}

__global__ void __launch_bounds__(256)
fused_sparse_then_fill_v8_d128(const float* __restrict__ z1,
                               const float* __restrict__ z2,
                               const int*  __restrict__ cls,
                               const int*  __restrict__ batch,
                               float* __restrict__ out,
                               int N)
{
    __shared__ int   scol[8][CAP];   // 8 warps per block
    __shared__ float sval[8][CAP];

    const int lane = threadIdx.x & 31;
    const int w    = threadIdx.x >> 5;
    const int row  = (blockIdx.x * blockDim.x + threadIdx.x) >> 5;
    if (row >= N) return;

    // ---------------- phase 1: sparse dots -> SMEM staging ----------------
    int k = 0;                         // uniform across the warp
    const int ci = cls[row];
    if (!(ci >= 24 && ci <= 26)) {
        const int bi = batch[row];
        const int lo = lower_bound_dev(batch, N, bi);
        const int hi = upper_bound_dev(batch, N, bi);
        const float4 a  = reinterpret_cast<const float4*>(z1 + (size_t)row * 128)[lane];
        const float4 zv = make_float4(0.f, 0.f, 0.f, 0.f);

        for (int jb = lo; jb < hi; jb += 32) {
            const int j = jb + lane;
            const bool p = (j < hi) && (j != row) && (cls[j] == ci);
            unsigned m = __ballot_sync(0xffffffffu, p);
            while (m) {
                // peel up to 4 matches -> 4 independent load/reduce chains
                int jj0 = jb + __ffs(m) - 1; m &= m - 1;
                int jj1 = -1, jj2 = -1, jj3 = -1;
                if (m) { jj1 = jb + __ffs(m) - 1; m &= m - 1; }
                if (m) { jj2 = jb + __ffs(m) - 1; m &= m - 1; }
                if (m) { jj3 = jb + __ffs(m) - 1; m &= m - 1; }

                float4 v0 = reinterpret_cast<const float4*>(z2 + (size_t)jj0 * 128)[lane];
                float4 v1 = (jj1 >= 0) ? reinterpret_cast<const float4*>(z2 + (size_t)jj1 * 128)[lane] : zv;
                float4 v2 = (jj2 >= 0) ? reinterpret_cast<const float4*>(z2 + (size_t)jj2 * 128)[lane] : zv;
                float4 v3 = (jj3 >= 0) ? reinterpret_cast<const float4*>(z2 + (size_t)jj3 * 128)[lane] : zv;

                float d0 = a.x * v0.x + a.y * v0.y + a.z * v0.z + a.w * v0.w;
                float d1 = a.x * v1.x + a.y * v1.y + a.z * v1.z + a.w * v1.w;
                float d2 = a.x * v2.x + a.y * v2.y + a.z * v2.z + a.w * v2.w;
                float d3 = a.x * v3.x + a.y * v3.y + a.z * v3.z + a.w * v3.w;

                d0 = warp_reduce_add(d0);
                d1 = warp_reduce_add(d1);
                d2 = warp_reduce_add(d2);
                d3 = warp_reduce_add(d3);

                if (lane == 0) {
                    if (k < CAP)                 { scol[w][k]     = jj0; sval[w][k]     = d0; }
                    if (jj1 >= 0 && k + 1 < CAP) { scol[w][k + 1] = jj1; sval[w][k + 1] = d1; }
                    if (jj2 >= 0 && k + 2 < CAP) { scol[w][k + 2] = jj2; sval[w][k + 2] = d2; }
                    if (jj3 >= 0 && k + 3 < CAP) { scol[w][k + 3] = jj3; sval[w][k + 3] = d3; }
                }
                k += 1 + (jj1 >= 0) + (jj2 >= 0) + (jj3 >= 0);
            }
        }
    }
    __syncwarp();   // staging visible warp-wide before fill

    // ------ phase 2: zero-fill this row with 256-bit streaming stores -----
    {
        float* orow = out + (size_t)row * (size_t)N;
        const int n8 = N >> 3;                 // 256-bit elements per row
        #pragma unroll 8
        for (int i = lane; i < n8; i += 32)
            stg256_zero_cs(orow + (size_t)i * 8);
    }
    __syncwarp();   // order fill stores before value overwrites (cross-lane)

    // ---------------- phase 3: overwrite staged values (SMEM only) --------
    float* orow = out + (size_t)row * (size_t)N;
    const int kk = min(k, CAP);
    for (int s = lane; s < kk; s += 32)
        orow[scol[w][s]] = sval[w][s];

    // ---------------- overflow slow path (never expected) -----------------
    if (k > CAP) {
        const int bi = batch[row];
        const int lo = lower_bound_dev(batch, N, bi);
        const int hi = upper_bound_dev(batch, N, bi);
        const float4 a = reinterpret_cast<const float4*>(z1 + (size_t)row * 128)[lane];
        for (int jb = lo; jb < hi; jb += 32) {
            const int j = jb + lane;
            const bool p = (j < hi) && (j != row) && (cls[j] == ci);
            unsigned m = __ballot_sync(0xffffffffu, p);
            while (m) {
                const int b = __ffs(m) - 1; m &= m - 1;
                const int jj = jb + b;
                const float4 v = reinterpret_cast<const float4*>(z2 + (size_t)jj * 128)[lane];
                float d = a.x * v.x + a.y * v.y + a.z * v.z + a.w * v.w;
                d = warp_reduce_add(d);
                if (lane == 0) orow[jj] = d;
            }
        }
    }
}

// ----------------- generic fallback (any D): memset + direct scatter -------
__global__ void seg_decoder_sparse_generic(const float* __restrict__ z1,
                                           const float* __restrict__ z2,
                                           const int*  __restrict__ cls,
                                           const int*  __restrict__ batch,
                                           float* __restrict__ out,
                                           int N, int D)
{
    const int lane = threadIdx.x & 31;
    const int row  = (blockIdx.x * blockDim.x + threadIdx.x) >> 5;
    if (row >= N) return;

    const int ci = cls[row];
    if (ci >= 24 && ci <= 26) return;
    const int bi = batch[row];
    const int lo = lower_bound_dev(batch, N, bi);
    const int hi = upper_bound_dev(batch, N, bi);
    const float* arow = z1 + (size_t)row * D;
    float* orow = out + (size_t)row * (size_t)N;

    for (int jb = lo; jb < hi; jb += 32) {
        const int j = jb + lane;
        const bool p = (j < hi) && (j != row) && (cls[j] == ci);
        unsigned m = __ballot_sync(0xffffffffu, p);
        while (m) {
            const int b = __ffs(m) - 1; m &= m - 1;
            const int jj = jb + b;
            const float* vrow = z2 + (size_t)jj * D;
            float d = 0.f;
            for (int kk = lane; kk < D; kk += 32) d += arow[kk] * vrow[kk];
            d = warp_reduce_add(d);
            if (lane == 0) orow[jj] = d;
        }
    }
}

extern "C" void kernel_launch(void* const* d_in, const int* in_sizes, int n_in,
                              void* d_out, int out_size)
{
    const float* z1    = (const float*)d_in[0];
    const float* z2    = (const float*)d_in[1];
    const int*   cls   = (const int*)d_in[2];
    const int*   batch = (const int*)d_in[3];
    float*       out   = (float*)d_out;

    const int N = in_sizes[2];
    const int D = in_sizes[0] / N;

    if (D == 128 && (N & 7) == 0) {
        const int blocks = (N * 32 + 255) / 256;   // one warp per row
        fused_sparse_then_fill_v8_d128<<<blocks, 256>>>(z1, z2, cls, batch, out, N);
    } else {
        cudaMemsetAsync(out, 0, (size_t)out_size * sizeof(float));
        const int blocks = (N * 32 + 255) / 256;
        seg_decoder_sparse_generic<<<blocks, 256>>>(z1, z2, cls, batch, out, N, D);
    }
}

// round 13
// speedup vs baseline: 1.0435x; 1.0392x over previous
#include <cuda_runtime.h>
#include <cuda_bf16.h>

// out[i,j] = dot(z1[i], z2[j]) if batch[i]==batch[j] && cls[i]==cls[j]
//            && !(24<=cls[i]<=26) && i!=j, else 0.
//
// Fused kernel, warp per row:
//   phase 1a: OUTWARD WARP SCAN from row (batch sorted, row is inside its own
//             segment): coalesced 32-chunks, ballot for boundary + matches at
//             once. Replaces two 14-step serial binary searches (the old
//             prologue bottleneck).
//   phase 1b: dots over collected columns, 4-way ILP -> SMEM staging
//   phase 2:  zero-fill row with 256-bit streaming stores (~7TB/s aggregate)
//   phase 3:  overwrite staged values (SMEM reads only)

#define CAP 64               // staged matches per row (avg ~9.5; tail-safe)
#define FULLM 0xffffffffu

__device__ __forceinline__ int lower_bound_dev(const int* __restrict__ a, int n, int v) {
    int lo = 0, hi = n;
    while (lo < hi) { int m = (lo + hi) >> 1; if (a[m] < v) lo = m + 1; else hi = m; }
    return lo;
}
__device__ __forceinline__ int upper_bound_dev(const int* __restrict__ a, int n, int v) {
    int lo = 0, hi = n;
    while (lo < hi) { int m = (lo + hi) >> 1; if (a[m] <= v) lo = m + 1; else hi = m; }
    return lo;
}
__device__ __forceinline__ float warp_reduce_add(float d) {
    d += __shfl_xor_sync(FULLM, d, 16);
    d += __shfl_xor_sync(FULLM, d, 8);
    d += __shfl_xor_sync(FULLM, d, 4);
    d += __shfl_xor_sync(FULLM, d, 2);
    d += __shfl_xor_sync(FULLM, d, 1);
    return d;
}
__device__ __forceinline__ void stg256_zero_cs(float* p) {
    asm volatile("st.global.cs.v8.b32 [%0], {%1,%1,%1,%1,%1,%1,%1,%1};"
                 :: "l"(p), "r"(0u) : "memory");
}

__global__ void __launch_bounds__(256)
fused_outscan_d128(const float* __restrict__ z1,
                   const float* __restrict__ z2,
                   const int*  __restrict__ cls,
                   const int*  __restrict__ batch,
                   float* __restrict__ out,
                   int N)
{
    __shared__ int   scol[8][CAP];
    __shared__ float sval[8][CAP];

    const int lane = threadIdx.x & 31;
    const int w    = threadIdx.x >> 5;
    const int row  = (blockIdx.x * blockDim.x + threadIdx.x) >> 5;
    if (row >= N) return;

    const int ci = cls[row];
    const bool excluded = (ci >= 24 && ci <= 26);
    int k = 0;

    if (!excluded) {
        const int bi = batch[row];

        // ---- phase 1a: outward scan, collect match columns ----------------
        // forward: j = row+1, row+2, ...
        for (int jb = row + 1; jb < N; jb += 32) {
            const int j = jb + lane;
            const bool inb = (j < N);
            const int bj = inb ? batch[j] : (bi ^ 1);
            const int cj = inb ? cls[j]   : -1;
            const bool sg = (bj == bi);
            const unsigned diffm = __ballot_sync(FULLM, !sg);
            unsigned mm = __ballot_sync(FULLM, sg && (cj == ci));
            if (diffm) {
                const int pos = __ffs(diffm) - 1;          // first out-of-segment lane
                mm &= (pos < 32) ? ((1u << pos) - 1u) : FULLM;
            }
            if (mm & (1u << lane)) {
                const int slot = k + __popc(mm & ((1u << lane) - 1u));
                if (slot < CAP) scol[w][slot] = j;
            }
            k += __popc(mm);
            if (diffm) break;
        }
        // backward: j = row-32..row-1, then next chunk below, ...
        for (int jb = row - 32; ; jb -= 32) {
            const int j = jb + lane;
            const bool inb = (j >= 0);
            const int bj = inb ? batch[j] : (bi ^ 1);
            const int cj = inb ? cls[j]   : -1;
            const bool sg = (bj == bi);
            const unsigned diffm = __ballot_sync(FULLM, !sg);
            unsigned mm = __ballot_sync(FULLM, sg && (cj == ci));
            if (diffm) {
                const int pos = 31 - __clz(diffm);          // last out-of-segment lane
                mm &= ~((pos < 31) ? ((1u << (pos + 1)) - 1u) : FULLM);
                if (pos == 31) mm = 0;
            }
            if (mm & (1u << lane)) {
                const int slot = k + __popc(mm & ((1u << lane) - 1u));
                if (slot < CAP) scol[w][slot] = j;
            }
            k += __popc(mm);
            if (diffm) break;
        }
    }
    __syncwarp();
    const int kk = min(k, CAP);

    // ---- phase 1b: dots over collected columns (4-way ILP) ---------------
    if (kk > 0) {
        const float4 a = reinterpret_cast<const float4*>(z1 + (size_t)row * 128)[lane];
        for (int s = 0; s < kk; s += 4) {
            const int jj0 = scol[w][s];
            const int jj1 = (s + 1 < kk) ? scol[w][s + 1] : jj0;
            const int jj2 = (s + 2 < kk) ? scol[w][s + 2] : jj0;
            const int jj3 = (s + 3 < kk) ? scol[w][s + 3] : jj0;

            const float4 b0 = reinterpret_cast<const float4*>(z2 + (size_t)jj0 * 128)[lane];
            const float4 b1 = reinterpret_cast<const float4*>(z2 + (size_t)jj1 * 128)[lane];
            const float4 b2 = reinterpret_cast<const float4*>(z2 + (size_t)jj2 * 128)[lane];
            const float4 b3 = reinterpret_cast<const float4*>(z2 + (size_t)jj3 * 128)[lane];

            float d0 = a.x * b0.x + a.y * b0.y + a.z * b0.z + a.w * b0.w;
            float d1 = a.x * b1.x + a.y * b1.y + a.z * b1.z + a.w * b1.w;
            float d2 = a.x * b2.x + a.y * b2.y + a.z * b2.z + a.w * b2.w;
            float d3 = a.x * b3.x + a.y * b3.y + a.z * b3.z + a.w * b3.w;

            d0 = warp_reduce_add(d0);
            d1 = warp_reduce_add(d1);
            d2 = warp_reduce_add(d2);
            d3 = warp_reduce_add(d3);

            if (lane == 0) {
                sval[w][s] = d0;
                if (s + 1 < kk) sval[w][s + 1] = d1;
                if (s + 2 < kk) sval[w][s + 2] = d2;
                if (s + 3 < kk) sval[w][s + 3] = d3;
            }
        }
    }
    __syncwarp();

    // ---- phase 2: zero-fill this row (256-bit streaming stores) ----------
    {
        float* orow = out + (size_t)row * (size_t)N;
        const int n8 = N >> 3;
        #pragma unroll 8
        for (int i = lane; i < n8; i += 32)
            stg256_zero_cs(orow + (size_t)i * 8);
    }
    __syncwarp();

    // ---- phase 3: overwrite staged values (SMEM only) --------------------
    float* orow = out + (size_t)row * (size_t)N;
    for (int s = lane; s < kk; s += 32)
        orow[scol[w][s]] = sval[w][s];

    // ---- overflow slow path (k > CAP; never expected) --------------------
    if (k > CAP) {
        const int bi = batch[row];
        const int lo = lower_bound_dev(batch, N, bi);
        const int hi = upper_bound_dev(batch, N, bi);
        const float4 a = reinterpret_cast<const float4*>(z1 + (size_t)row * 128)[lane];
        for (int jb = lo; jb < hi; jb += 32) {
            const int j = jb + lane;
            const bool p = (j < hi) && (j != row) && (cls[j] == ci);
            unsigned m = __ballot_sync(FULLM, p);
            while (m) {
                const int b = __ffs(m) - 1; m &= m - 1;
                const int jj = jb + b;
                const float4 v = reinterpret_cast<const float4*>(z2 + (size_t)jj * 128)[lane];
                float d = a.x * v.x + a.y * v.y + a.z * v.z + a.w * v.w;
                d = warp_reduce_add(d);
                if (lane == 0) orow[jj] = d;
            }
        }
    }
}

// ----------------- generic fallback (any D): memset + direct scatter -------
__global__ void seg_decoder_sparse_generic(const float* __restrict__ z1,
                                           const float* __restrict__ z2,
                                           const int*  __restrict__ cls,
                                           const int*  __restrict__ batch,
                                           float* __restrict__ out,
                                           int N, int D)
{
    const int lane = threadIdx.x & 31;
    const int row  = (blockIdx.x * blockDim.x + threadIdx.x) >> 5;
    if (row >= N) return;

    const int ci = cls[row];
    if (ci >= 24 && ci <= 26) return;
    const int bi = batch[row];
    const int lo = lower_bound_dev(batch, N, bi);
    const int hi = upper_bound_dev(batch, N, bi);
    const float* arow = z1 + (size_t)row * D;
    float* orow = out + (size_t)row * (size_t)N;

    for (int jb = lo; jb < hi; jb += 32) {
        const int j = jb + lane;
        const bool p = (j < hi) && (j != row) && (cls[j] == ci);
        unsigned m = __ballot_sync(FULLM, p);
        while (m) {
            const int b = __ffs(m) - 1; m &= m - 1;
            const int jj = jb + b;
            const float* vrow = z2 + (size_t)jj * D;
            float d = 0.f;
            for (int kk = lane; kk < D; kk += 32) d += arow[kk] * vrow[kk];
            d = warp_reduce_add(d);
            if (lane == 0) orow[jj] = d;
        }
    }
}

extern "C" void kernel_launch(void* const* d_in, const int* in_sizes, int n_in,
                              void* d_out, int out_size)
{
    const float* z1    = (const float*)d_in[0];
    const float* z2    = (const float*)d_in[1];
    const int*   cls   = (const int*)d_in[2];
    const int*   batch = (const int*)d_in[3];
    float*       out   = (float*)d_out;

    const int N = in_sizes[2];
    const int D = in_sizes[0] / N;

    if (D == 128 && (N & 7) == 0) {
        const int blocks = (N * 32 + 255) / 256;   // one warp per row
        fused_outscan_d128<<<blocks, 256>>>(z1, z2, cls, batch, out, N);
    } else {
        cudaMemsetAsync(out, 0, (size_t)out_size * sizeof(float));
        const int blocks = (N * 32 + 255) / 256;
        seg_decoder_sparse_generic<<<blocks, 256>>>(z1, z2, cls, batch, out, N, D);
    }
}

// round 14
// speedup vs baseline: 1.0609x; 1.0167x over previous
#include <cuda_runtime.h>
#include <cuda_bf16.h>

// out[i,j] = dot(z1[i], z2[j]) if batch[i]==batch[j] && cls[i]==cls[j]
//            && !(24<=cls[i]<=26) && i!=j, else 0.
//
// Two graph nodes:
//   1. cudaMemsetAsync(out, 0)  — CE fill @ ~7.2TB/s (~84us; SM fills cap
//      at ~5.7TB/s, measured across rounds 1-13)
//   2. direct sparse kernel — warp per row:
//        a) outward coalesced scan from `row` (batch sorted; row is inside
//           its own segment) -> match columns in SMEM. No binary searches.
//        b) dots in ILP-4 groups (4 independent LDG->FFMA->shuffle chains)
//           -> store straight into the zeroed output.
//      This replaces round-2's 27us kernel (serial binary searches + one
//      chain at a time) with ~4x the memory-level parallelism.

#define CAP 64               // match columns per row (avg ~9.5; tail-safe)
#define FULLM 0xffffffffu

__device__ __forceinline__ int lower_bound_dev(const int* __restrict__ a, int n, int v) {
    int lo = 0, hi = n;
    while (lo < hi) { int m = (lo + hi) >> 1; if (a[m] < v) lo = m + 1; else hi = m; }
    return lo;
}
__device__ __forceinline__ int upper_bound_dev(const int* __restrict__ a, int n, int v) {
    int lo = 0, hi = n;
    while (lo < hi) { int m = (lo + hi) >> 1; if (a[m] <= v) lo = m + 1; else hi = m; }
    return lo;
}
__device__ __forceinline__ float warp_reduce_add(float d) {
    d += __shfl_xor_sync(FULLM, d, 16);
    d += __shfl_xor_sync(FULLM, d, 8);
    d += __shfl_xor_sync(FULLM, d, 4);
    d += __shfl_xor_sync(FULLM, d, 2);
    d += __shfl_xor_sync(FULLM, d, 1);
    return d;
}

__global__ void __launch_bounds__(256)
sparse_direct_d128(const float* __restrict__ z1,
                   const float* __restrict__ z2,
                   const int*  __restrict__ cls,
                   const int*  __restrict__ batch,
                   float* __restrict__ out,
                   int N)
{
    __shared__ int scol[8][CAP];

    const int lane = threadIdx.x & 31;
    const int w    = threadIdx.x >> 5;
    const int row  = (blockIdx.x * blockDim.x + threadIdx.x) >> 5;
    if (row >= N) return;

    const int ci = cls[row];
    if (ci >= 24 && ci <= 26) return;       // row stays zero
    const int bi = batch[row];
    int k = 0;

    // ---- phase a: outward coalesced scan, collect match columns ----------
    for (int jb = row + 1; jb < N; jb += 32) {           // forward
        const int j = jb + lane;
        const bool inb = (j < N);
        const int bj = inb ? batch[j] : (bi ^ 1);
        const int cj = inb ? cls[j]   : -1;
        const bool sg = (bj == bi);
        const unsigned diffm = __ballot_sync(FULLM, !sg);
        unsigned mm = __ballot_sync(FULLM, sg && (cj == ci));
        if (diffm) {
            const int pos = __ffs(diffm) - 1;            // first out-of-segment lane
            mm &= (pos < 32) ? ((1u << pos) - 1u) : FULLM;
        }
        if (mm & (1u << lane)) {
            const int slot = k + __popc(mm & ((1u << lane) - 1u));
            if (slot < CAP) scol[w][slot] = j;
        }
        k += __popc(mm);
        if (diffm) break;
    }
    for (int jb = row - 32; ; jb -= 32) {                // backward
        const int j = jb + lane;
        const bool inb = (j >= 0);
        const int bj = inb ? batch[j] : (bi ^ 1);
        const int cj = inb ? cls[j]   : -1;
        const bool sg = (bj == bi);
        const unsigned diffm = __ballot_sync(FULLM, !sg);
        unsigned mm = __ballot_sync(FULLM, sg && (cj == ci));
        if (diffm) {
            const int pos = 31 - __clz(diffm);           // last out-of-segment lane
            mm &= ~((pos < 31) ? ((1u << (pos + 1)) - 1u) : FULLM);
            if (pos == 31) mm = 0;
        }
        if (mm & (1u << lane)) {
            const int slot = k + __popc(mm & ((1u << lane) - 1u));
            if (slot < CAP) scol[w][slot] = j;
        }
        k += __popc(mm);
        if (diffm) break;
    }
    __syncwarp();
    const int kk = min(k, CAP);

    // ---- phase b: ILP-4 dots, store directly into zeroed output ----------
    float* orow = out + (size_t)row * (size_t)N;
    if (kk > 0) {
        const float4 a = reinterpret_cast<const float4*>(z1 + (size_t)row * 128)[lane];
        for (int s = 0; s < kk; s += 4) {
            const int jj0 = scol[w][s];
            const int jj1 = (s + 1 < kk) ? scol[w][s + 1] : jj0;
            const int jj2 = (s + 2 < kk) ? scol[w][s + 2] : jj0;
            const int jj3 = (s + 3 < kk) ? scol[w][s + 3] : jj0;

            const float4 b0 = reinterpret_cast<const float4*>(z2 + (size_t)jj0 * 128)[lane];
            const float4 b1 = reinterpret_cast<const float4*>(z2 + (size_t)jj1 * 128)[lane];
            const float4 b2 = reinterpret_cast<const float4*>(z2 + (size_t)jj2 * 128)[lane];
            const float4 b3 = reinterpret_cast<const float4*>(z2 + (size_t)jj3 * 128)[lane];

            float d0 = a.x * b0.x + a.y * b0.y + a.z * b0.z + a.w * b0.w;
            float d1 = a.x * b1.x + a.y * b1.y + a.z * b1.z + a.w * b1.w;
            float d2 = a.x * b2.x + a.y * b2.y + a.z * b2.z + a.w * b2.w;
            float d3 = a.x * b3.x + a.y * b3.y + a.z * b3.z + a.w * b3.w;

            d0 = warp_reduce_add(d0);
            d1 = warp_reduce_add(d1);
            d2 = warp_reduce_add(d2);
            d3 = warp_reduce_add(d3);

            if (lane == 0) {
                orow[jj0] = d0;
                if (s + 1 < kk) orow[jj1] = d1;
                if (s + 2 < kk) orow[jj2] = d2;
                if (s + 3 < kk) orow[jj3] = d3;
            }
        }
    }

    // ---- overflow slow path (k > CAP; never expected) --------------------
    if (k > CAP) {
        const int lo = lower_bound_dev(batch, N, bi);
        const int hi = upper_bound_dev(batch, N, bi);
        const float4 a = reinterpret_cast<const float4*>(z1 + (size_t)row * 128)[lane];
        for (int jb = lo; jb < hi; jb += 32) {
            const int j = jb + lane;
            const bool p = (j < hi) && (j != row) && (cls[j] == ci);
            unsigned m = __ballot_sync(FULLM, p);
            while (m) {
                const int b = __ffs(m) - 1; m &= m - 1;
                const int jj = jb + b;
                const float4 v = reinterpret_cast<const float4*>(z2 + (size_t)jj * 128)[lane];
                float d = a.x * v.x + a.y * v.y + a.z * v.z + a.w * v.w;
                d = warp_reduce_add(d);
                if (lane == 0) orow[jj] = d;
            }
        }
    }
}

// ----------------- generic fallback (any D): memset + direct scatter -------
__global__ void seg_decoder_sparse_generic(const float* __restrict__ z1,
                                           const float* __restrict__ z2,
                                           const int*  __restrict__ cls,
                                           const int*  __restrict__ batch,
                                           float* __restrict__ out,
                                           int N, int D)
{
    const int lane = threadIdx.x & 31;
    const int row  = (blockIdx.x * blockDim.x + threadIdx.x) >> 5;
    if (row >= N) return;

    const int ci = cls[row];
    if (ci >= 24 && ci <= 26) return;
    const int bi = batch[row];
    const int lo = lower_bound_dev(batch, N, bi);
    const int hi = upper_bound_dev(batch, N, bi);
    const float* arow = z1 + (size_t)row * D;
    float* orow = out + (size_t)row * (size_t)N;

    for (int jb = lo; jb < hi; jb += 32) {
        const int j = jb + lane;
        const bool p = (j < hi) && (j != row) && (cls[j] == ci);
        unsigned m = __ballot_sync(FULLM, p);
        while (m) {
            const int b = __ffs(m) - 1; m &= m - 1;
            const int jj = jb + b;
            const float* vrow = z2 + (size_t)jj * D;
            float d = 0.f;
            for (int kk = lane; kk < D; kk += 32) d += arow[kk] * vrow[kk];
            d = warp_reduce_add(d);
            if (lane == 0) orow[jj] = d;
        }
    }
}

extern "C" void kernel_launch(void* const* d_in, const int* in_sizes, int n_in,
                              void* d_out, int out_size)
{
    const float* z1    = (const float*)d_in[0];
    const float* z2    = (const float*)d_in[1];
    const int*   cls   = (const int*)d_in[2];
    const int*   batch = (const int*)d_in[3];
    float*       out   = (float*)d_out;

    const int N = in_sizes[2];
    const int D = in_sizes[0] / N;

    cudaMemsetAsync(out, 0, (size_t)out_size * sizeof(float));

    const int blocks = (N * 32 + 255) / 256;   // one warp per row
    if (D == 128) {
        sparse_direct_d128<<<blocks, 256>>>(z1, z2, cls, batch, out, N);
    } else {
        seg_decoder_sparse_generic<<<blocks, 256>>>(z1, z2, cls, batch, out, N, D);
    }
}

// round 15
// speedup vs baseline: 1.0645x; 1.0034x over previous
#include <cuda_runtime.h>
#include <cuda_bf16.h>

// out[i,j] = dot(z1[i], z2[j]) if batch[i]==batch[j] && cls[i]==cls[j]
//            && !(24<=cls[i]<=26) && i!=j, else 0.
//
// Two graph nodes:
//   1. cudaMemsetAsync(out, 0)       — CE fill @ ~7.2TB/s (~84us)
//   2. sparse kernel, warp per row:
//        a) SPECULATIVE scan: 8 fwd + 8 bwd chunk loads (256 cols each way,
//           covering the ~256-wide sorted-batch segment) issued up front as
//           independent clamped loads; ballot/boundary logic runs on
//           registers. Kills the serial 8-iteration load chain of round 14.
//        b) ILP-8 dot groups -> direct stores into the zeroed output.

#define CAP   64             // match columns per row (avg ~9.5; tail-safe)
#define SPAN  8              // speculative chunks each direction (8*32 cols)
#define FULLM 0xffffffffu

__device__ __forceinline__ int lower_bound_dev(const int* __restrict__ a, int n, int v) {
    int lo = 0, hi = n;
    while (lo < hi) { int m = (lo + hi) >> 1; if (a[m] < v) lo = m + 1; else hi = m; }
    return lo;
}
__device__ __forceinline__ int upper_bound_dev(const int* __restrict__ a, int n, int v) {
    int lo = 0, hi = n;
    while (lo < hi) { int m = (lo + hi) >> 1; if (a[m] <= v) lo = m + 1; else hi = m; }
    return lo;
}
__device__ __forceinline__ float warp_reduce_add(float d) {
    d += __shfl_xor_sync(FULLM, d, 16);
    d += __shfl_xor_sync(FULLM, d, 8);
    d += __shfl_xor_sync(FULLM, d, 4);
    d += __shfl_xor_sync(FULLM, d, 2);
    d += __shfl_xor_sync(FULLM, d, 1);
    return d;
}

__global__ void __launch_bounds__(256)
sparse_spec_d128(const float* __restrict__ z1,
                 const float* __restrict__ z2,
                 const int*  __restrict__ cls,
                 const int*  __restrict__ batch,
                 float* __restrict__ out,
                 int N)
{
    __shared__ int scol[8][CAP];

    const int lane = threadIdx.x & 31;
    const int w    = threadIdx.x >> 5;
    const int row  = (blockIdx.x * blockDim.x + threadIdx.x) >> 5;
    if (row >= N) return;

    const int ci = cls[row];
    if (ci >= 24 && ci <= 26) return;       // row stays zero
    const int bi = batch[row];
    int k = 0;

    // ---- phase a: speculative loads (independent, maximal MLP) -----------
    int bF[SPAN], cF[SPAN], bB[SPAN], cB[SPAN];
    #pragma unroll
    for (int c = 0; c < SPAN; c++) {
        const int jf = row + 1 + c * 32 + lane;
        const int jfc = (jf < N) ? jf : (N - 1);
        bF[c] = batch[jfc];  cF[c] = cls[jfc];
        const int jb = row - 32 * (c + 1) + lane;
        const int jbc = (jb >= 0) ? jb : 0;
        bB[c] = batch[jbc];  cB[c] = cls[jbc];
    }

    // ---- forward ballot pass on registers --------------------------------
    bool doneF = false;
    #pragma unroll
    for (int c = 0; c < SPAN; c++) {
        if (doneF) continue;                        // warp-uniform
        const int j = row + 1 + c * 32 + lane;
        const bool sg = (j < N) && (bF[c] == bi);
        const unsigned diffm = __ballot_sync(FULLM, !sg);
        unsigned mm = __ballot_sync(FULLM, sg && (cF[c] == ci));
        if (diffm) {
            const int pos = __ffs(diffm) - 1;
            mm &= (1u << pos) - 1u;                 // pos<32 guaranteed
        }
        if (mm & (1u << lane)) {
            const int slot = k + __popc(mm & ((1u << lane) - 1u));
            if (slot < CAP) scol[w][slot] = j;
        }
        k += __popc(mm);
        if (diffm) doneF = true;
    }
    if (!doneF) {                                   // rare: segment > 256 fwd
        for (int jb0 = row + 1 + SPAN * 32; jb0 < N; jb0 += 32) {
            const int j = jb0 + lane;
            const bool sg = (j < N) && (batch[(j < N) ? j : (N - 1)] == bi);
            const unsigned diffm = __ballot_sync(FULLM, !sg);
            unsigned mm = __ballot_sync(FULLM, sg && (cls[(j < N) ? j : (N - 1)] == ci));
            if (diffm) { const int pos = __ffs(diffm) - 1; mm &= (1u << pos) - 1u; }
            if (mm & (1u << lane)) {
                const int slot = k + __popc(mm & ((1u << lane) - 1u));
                if (slot < CAP) scol[w][slot] = j;
            }
            k += __popc(mm);
            if (diffm) break;
        }
    }

    // ---- backward ballot pass on registers -------------------------------
    bool doneB = false;
    #pragma unroll
    for (int c = 0; c < SPAN; c++) {
        if (doneB) continue;                        // warp-uniform
        const int j = row - 32 * (c + 1) + lane;
        const bool sg = (j >= 0) && (bB[c] == bi);
        const unsigned diffm = __ballot_sync(FULLM, !sg);
        unsigned mm = __ballot_sync(FULLM, sg && (cB[c] == ci));
        if (diffm) {
            const int pos = 31 - __clz(diffm);      // last out-of-segment lane
            mm = (pos == 31) ? 0u : (mm & ~((1u << (pos + 1)) - 1u));
        }
        if (mm & (1u << lane)) {
            const int slot = k + __popc(mm & ((1u << lane) - 1u));
            if (slot < CAP) scol[w][slot] = j;
        }
        k += __popc(mm);
        if (diffm) doneB = true;
    }
    if (!doneB) {                                   // rare: segment > 256 bwd
        for (int jb0 = row - 32 * (SPAN + 1); ; jb0 -= 32) {
            const int j = jb0 + lane;
            const int jc = (j >= 0) ? j : 0;
            const bool sg = (j >= 0) && (batch[jc] == bi);
            const unsigned diffm = __ballot_sync(FULLM, !sg);
            unsigned mm = __ballot_sync(FULLM, sg && (cls[jc] == ci));
            if (diffm) {
                const int pos = 31 - __clz(diffm);
                mm = (pos == 31) ? 0u : (mm & ~((1u << (pos + 1)) - 1u));
            }
            if (mm & (1u << lane)) {
                const int slot = k + __popc(mm & ((1u << lane) - 1u));
                if (slot < CAP) scol[w][slot] = j;
            }
            k += __popc(mm);
            if (diffm) break;
        }
    }
    __syncwarp();
    const int kk = min(k, CAP);

    // ---- phase b: ILP-8 dots, store directly into zeroed output ----------
    float* orow = out + (size_t)row * (size_t)N;
    if (kk > 0) {
        const float4 a = reinterpret_cast<const float4*>(z1 + (size_t)row * 128)[lane];
        for (int s = 0; s < kk; s += 8) {
            int jj[8];
            #pragma unroll
            for (int q = 0; q < 8; q++)
                jj[q] = (s + q < kk) ? scol[w][s + q] : scol[w][s];

            float4 b[8];
            #pragma unroll
            for (int q = 0; q < 8; q++)
                b[q] = reinterpret_cast<const float4*>(z2 + (size_t)jj[q] * 128)[lane];

            float d[8];
            #pragma unroll
            for (int q = 0; q < 8; q++)
                d[q] = a.x * b[q].x + a.y * b[q].y + a.z * b[q].z + a.w * b[q].w;
            #pragma unroll
            for (int q = 0; q < 8; q++)
                d[q] = warp_reduce_add(d[q]);

            if (lane == 0) {
                #pragma unroll
                for (int q = 0; q < 8; q++)
                    if (s + q < kk) orow[jj[q]] = d[q];
            }
        }
    }

    // ---- overflow slow path (k > CAP; never expected) --------------------
    if (k > CAP) {
        const int lo = lower_bound_dev(batch, N, bi);
        const int hi = upper_bound_dev(batch, N, bi);
        const float4 a = reinterpret_cast<const float4*>(z1 + (size_t)row * 128)[lane];
        for (int jb0 = lo; jb0 < hi; jb0 += 32) {
            const int j = jb0 + lane;
            const bool p = (j < hi) && (j != row) && (cls[j] == ci);
            unsigned m = __ballot_sync(FULLM, p);
            while (m) {
                const int bpos = __ffs(m) - 1; m &= m - 1;
                const int jjv = jb0 + bpos;
                const float4 v = reinterpret_cast<const float4*>(z2 + (size_t)jjv * 128)[lane];
                float dd = a.x * v.x + a.y * v.y + a.z * v.z + a.w * v.w;
                dd = warp_reduce_add(dd);
                if (lane == 0) orow[jjv] = dd;
            }
        }
    }
}

// ----------------- generic fallback (any D): memset + direct scatter -------
__global__ void seg_decoder_sparse_generic(const float* __restrict__ z1,
                                           const float* __restrict__ z2,
                                           const int*  __restrict__ cls,
                                           const int*  __restrict__ batch,
                                           float* __restrict__ out,
                                           int N, int D)
{
    const int lane = threadIdx.x & 31;
    const int row  = (blockIdx.x * blockDim.x + threadIdx.x) >> 5;
    if (row >= N) return;

    const int ci = cls[row];
    if (ci >= 24 && ci <= 26) return;
    const int bi = batch[row];
    const int lo = lower_bound_dev(batch, N, bi);
    const int hi = upper_bound_dev(batch, N, bi);
    const float* arow = z1 + (size_t)row * D;
    float* orow = out + (size_t)row * (size_t)N;

    for (int jb = lo; jb < hi; jb += 32) {
        const int j = jb + lane;
        const bool p = (j < hi) && (j != row) && (cls[j] == ci);
        unsigned m = __ballot_sync(FULLM, p);
        while (m) {
            const int b = __ffs(m) - 1; m &= m - 1;
            const int jj = jb + b;
            const float* vrow = z2 + (size_t)jj * D;
            float d = 0.f;
            for (int kk = lane; kk < D; kk += 32) d += arow[kk] * vrow[kk];
            d = warp_reduce_add(d);
            if (lane == 0) orow[jj] = d;
        }
    }
}

extern "C" void kernel_launch(void* const* d_in, const int* in_sizes, int n_in,
                              void* d_out, int out_size)
{
    const float* z1    = (const float*)d_in[0];
    const float* z2    = (const float*)d_in[1];
    const int*   cls   = (const int*)d_in[2];
    const int*   batch = (const int*)d_in[3];
    float*       out   = (float*)d_out;

    const int N = in_sizes[2];
    const int D = in_sizes[0] / N;

    cudaMemsetAsync(out, 0, (size_t)out_size * sizeof(float));

    const int blocks = (N * 32 + 255) / 256;   // one warp per row
    if (D == 128) {
        sparse_spec_d128<<<blocks, 256>>>(z1, z2, cls, batch, out, N);
    } else {
        seg_decoder_sparse_generic<<<blocks, 256>>>(z1, z2, cls, batch, out, N, D);
    }
}